// round 10
// baseline (speedup 1.0000x reference)
#include <cuda_runtime.h>
#include <cuda_fp16.h>

#define NN 100000
#define HH 64
#define EMAX 1600000
#define BN_EPS 1e-5f

// ---- scratch ----
__device__ uint4  g_h16[NN * 8];         // hs in fp16: 64 halves = 128B/row
__device__ float4 g_bufB[NN * HH / 4];   // fp32 accumulator
__device__ float4 g_bufC[NN * HH / 4];   // layer outputs (fp32)
__device__ int   g_src[EMAX];
__device__ int   g_dst[EMAX];
__device__ int   g_degi[NN];
__device__ int   g_is64;
__device__ float g_stats1[128 * 32];     // padded: channel ch at [ch*32]
__device__ float g_stats2[128 * 32];

// ---- launch 1: zero acc/deg/stats; block 0 detects int64 vs int32 ----
__global__ void k_pre(const unsigned int* __restrict__ ei) {
    int i = blockIdx.x * 256 + threadIdx.x;
    if (i < NN * HH / 4) g_bufB[i] = make_float4(0.f, 0.f, 0.f, 0.f);
    if (i < NN) g_degi[i] = 0;
    if (i < 128 * 32) { g_stats1[i] = 0.0f; g_stats2[i] = 0.0f; }
    if (blockIdx.x == 0) {
        __shared__ unsigned int s;
        if (threadIdx.x == 0) s = 0u;
        __syncthreads();
        atomicOr(&s, ei[threadIdx.x * 2 + 1]);   // high words if int64
        __syncthreads();
        if (threadIdx.x == 0) g_is64 = (s == 0u) ? 1 : 0;
    }
}

// ---- launch 2: convert indices to int32 + in-degree of dst ----
__global__ void k_cvtdeg(const void* __restrict__ ei, int E) {
    int e = blockIdx.x * 256 + threadIdx.x;
    if (e >= E) return;
    int s, d;
    if (g_is64) {
        const long long* p = (const long long*)ei;
        s = (int)p[e]; d = (int)p[e + E];
    } else {
        const int* p = (const int*)ei;
        s = p[e]; d = p[e + E];
    }
    g_src[e] = s;
    g_dst[e] = d;
    atomicAdd(&g_degi[d], 1);
}

// ---- GEMM: out[r] = ((a*X[r]+c) @ W) * dinv[r] + (bias + c@W)
// a,c computed per-block from BN stats (identity if stats==null).
// HOUT: write fp16 rows (hs); else fp32 float4 rows.
template <int NOUT, bool SCALE, bool HOUT>
__global__ void __launch_bounds__(128) k_gemm(
    const float* __restrict__ X, const float* __restrict__ Wg,
    const float* __restrict__ stats, const float* __restrict__ gamma,
    const float* __restrict__ beta,
    const float* __restrict__ bias, void* __restrict__ outv)
{
    extern __shared__ float sm[];
    float* Xs   = sm;                 // 128 * 65 (pad -> conflict-free)
    float* Ws   = sm + 128 * 65;      // 64 * NOUT (pre-scaled by a[k])
    float* Init = Ws + 64 * NOUT;     // NOUT
    __shared__ float sa[64], sc[64];

    const int t = threadIdx.x;
    const long row0 = (long)blockIdx.x * 128;

    if (t < 64) {
        float a = 1.0f, c = 0.0f;
        if (stats) {
            float mu  = stats[t * 32] * (1.0f / NN);
            float var = stats[(64 + t) * 32] * (1.0f / NN) - mu * mu;
            a = gamma[t] * rsqrtf(var + BN_EPS);
            c = beta[t] - mu * a;
        }
        sa[t] = a; sc[t] = c;
    }
    __syncthreads();

    #pragma unroll
    for (int i = 0; i < 16; i++) {
        int lin = t + i * 128;
        int r = lin >> 4, q = lin & 15;
        long gr = row0 + r;
        float4 v = (gr < NN) ? reinterpret_cast<const float4*>(X)[gr * 16 + q]
                             : make_float4(0.f, 0.f, 0.f, 0.f);
        float* p = &Xs[r * 65 + q * 4];
        p[0] = v.x; p[1] = v.y; p[2] = v.z; p[3] = v.w;
    }
    #pragma unroll
    for (int i = t; i < 16 * NOUT; i += 128) {
        int k = (i * 4) / NOUT;
        float a = sa[k];
        float4 w = reinterpret_cast<const float4*>(Wg)[i];
        reinterpret_cast<float4*>(Ws)[i] = make_float4(w.x * a, w.y * a, w.z * a, w.w * a);
    }
    if (t < NOUT) {
        float s = bias ? bias[t] : 0.0f;
        #pragma unroll 8
        for (int k = 0; k < 64; k++) s += sc[k] * Wg[k * NOUT + t];
        Init[t] = s;
    }
    __syncthreads();

    unsigned long long acc[NOUT / 2];
    #pragma unroll
    for (int j = 0; j < NOUT / 2; j++) {
        float2 iv = reinterpret_cast<const float2*>(Init)[j];
        asm("mov.b64 %0, {%1, %2};" : "=l"(acc[j]) : "f"(iv.x), "f"(iv.y));
    }
    const float* xr = &Xs[t * 65];
    #pragma unroll 4
    for (int k = 0; k < 64; k++) {
        float xv = xr[k];
        unsigned long long xx;
        asm("mov.b64 %0, {%1, %1};" : "=l"(xx) : "f"(xv));
        const unsigned long long* wr =
            reinterpret_cast<const unsigned long long*>(&Ws[k * NOUT]);
        #pragma unroll
        for (int j = 0; j < NOUT / 2; j++)
            asm("fma.rn.f32x2 %0, %1, %2, %0;" : "+l"(acc[j]) : "l"(xx), "l"(wr[j]));
    }

    long r = row0 + t;
    float rs = 1.0f;
    if (SCALE && r < NN) rs = rsqrtf((float)g_degi[r] + 1.0f);

    __syncthreads();   // Xs reuse as output staging
    if (HOUT) {
        // fp16 writeout: stage 32 half2 (u32) per row, stride 33
        unsigned int* S = reinterpret_cast<unsigned int*>(sm);
        #pragma unroll
        for (int j = 0; j < NOUT / 2; j++) {
            float lo, hi;
            asm("mov.b64 {%0, %1}, %2;" : "=f"(lo), "=f"(hi) : "l"(acc[j]));
            __half2 h = __floats2half2_rn(lo * rs, hi * rs);
            S[t * 33 + j] = *reinterpret_cast<unsigned int*>(&h);
        }
        __syncthreads();
        uint4* out = reinterpret_cast<uint4*>(outv);
        #pragma unroll
        for (int i = 0; i < 8; i++) {
            int lin = t + i * 128;
            int r2 = lin >> 3, q = lin & 7;
            long gr = row0 + r2;
            if (gr < NN) {
                unsigned int* p = &S[r2 * 33 + q * 4];
                uint4 w; w.x = p[0]; w.y = p[1]; w.z = p[2]; w.w = p[3];
                out[gr * 8 + q] = w;
            }
        }
    } else {
        #pragma unroll
        for (int j = 0; j < NOUT / 2; j++) {
            float lo, hi;
            asm("mov.b64 {%0, %1}, %2;" : "=f"(lo), "=f"(hi) : "l"(acc[j]));
            Xs[t * 65 + 2 * j]     = lo * rs;
            Xs[t * 65 + 2 * j + 1] = hi * rs;
        }
        __syncthreads();
        constexpr int Q = NOUT / 4;
        float* out = reinterpret_cast<float*>(outv);
        #pragma unroll
        for (int i = 0; i < Q; i++) {
            int lin = t + i * 128;
            int r2 = lin / Q, q = lin % Q;
            long gr = row0 + r2;
            if (gr < NN) {
                float* p = &Xs[r2 * 65 + q * 4];
                reinterpret_cast<float4*>(out)[gr * Q + q] =
                    make_float4(p[0], p[1], p[2], p[3]);
            }
        }
    }
}

__device__ __forceinline__ void red4(float4* p, float v0, float v1, float v2, float v3) {
    asm volatile("red.global.add.v4.f32 [%0], {%1,%2,%3,%4};"
                 :: "l"(p), "f"(v0), "f"(v1), "f"(v2), "f"(v3) : "memory");
}

// ---- launch 4 (PROFILED): scatter acc[dst] += fp16 hs[src], fp32 REDs ----
// 8 lanes/edge: lane loads 16B (8 halves), emits 2x red.v4.f32.
__global__ void k_scat(const uint4* __restrict__ hs, float4* __restrict__ acc, int E)
{
    long idx = (long)blockIdx.x * 256 + threadIdx.x;
    if (idx >= (long)E * 8) return;
    int e  = (int)(idx >> 3);
    int qh = (int)(idx & 7);
    int s = g_src[e], d = g_dst[e];
    uint4 hv = hs[(long)s * 8 + qh];
    __half2 h0 = *reinterpret_cast<__half2*>(&hv.x);
    __half2 h1 = *reinterpret_cast<__half2*>(&hv.y);
    __half2 h2 = *reinterpret_cast<__half2*>(&hv.z);
    __half2 h3 = *reinterpret_cast<__half2*>(&hv.w);
    float2 f0 = __half22float2(h0);
    float2 f1 = __half22float2(h1);
    float2 f2 = __half22float2(h2);
    float2 f3 = __half22float2(h3);
    float4* p = &acc[(long)d * 16 + qh * 2];
    red4(p,     f0.x, f0.y, f1.x, f1.y);
    red4(p + 1, f2.x, f2.y, f3.x, f3.y);
}

// ---- epilogue: h = relu(dinv*(acc+hs)+b); BN stats; optionally re-zero acc ----
template <bool ZERO_ACC>
__global__ void k_epi(const uint2* __restrict__ hs, float4* acc,
                      const float* __restrict__ bias,
                      float4* out, float* __restrict__ stats)
{
    __shared__ float ssum[64], ssq[64];
    int t = threadIdx.x;
    if (t < 64) { ssum[t] = 0.0f; ssq[t] = 0.0f; }
    __syncthreads();
    long idx = (long)blockIdx.x * 256 + t;
    if (idx < (long)NN * 16) {
        int v = (int)(idx >> 4);
        int q = (int)(idx & 15);
        float4 a = acc[idx];
        uint2 hv = hs[(long)v * 16 + q];           // 4 halves
        __half2 p0 = *reinterpret_cast<__half2*>(&hv.x);
        __half2 p1 = *reinterpret_cast<__half2*>(&hv.y);
        float2 f0 = __half22float2(p0);
        float2 f1 = __half22float2(p1);
        float di = rsqrtf((float)g_degi[v] + 1.0f);
        float4 b = reinterpret_cast<const float4*>(bias)[q];
        float4 o;
        o.x = fmaxf(fmaf(di, a.x + f0.x, b.x), 0.0f);
        o.y = fmaxf(fmaf(di, a.y + f0.y, b.y), 0.0f);
        o.z = fmaxf(fmaf(di, a.z + f1.x, b.z), 0.0f);
        o.w = fmaxf(fmaf(di, a.w + f1.y, b.w), 0.0f);
        out[idx] = o;
        if (ZERO_ACC) acc[idx] = make_float4(0.f, 0.f, 0.f, 0.f);
        int j = q * 4;
        atomicAdd(&ssum[j + 0], o.x); atomicAdd(&ssq[j + 0], o.x * o.x);
        atomicAdd(&ssum[j + 1], o.y); atomicAdd(&ssq[j + 1], o.y * o.y);
        atomicAdd(&ssum[j + 2], o.z); atomicAdd(&ssq[j + 2], o.z * o.z);
        atomicAdd(&ssum[j + 3], o.w); atomicAdd(&ssq[j + 3], o.w * o.w);
    }
    __syncthreads();
    if (t < 64) {
        atomicAdd(&stats[t * 32], ssum[t]);
        atomicAdd(&stats[(64 + t) * 32], ssq[t]);
    }
}

extern "C" void kernel_launch(void* const* d_in, const int* in_sizes, int n_in,
                              void* d_out, int out_size)
{
    const float* x      = (const float*)d_in[0];
    const void*  ei     = d_in[1];
    const float* W1     = (const float*)d_in[2];
    const float* b1     = (const float*)d_in[3];
    const float* gamma1 = (const float*)d_in[4];
    const float* beta1  = (const float*)d_in[5];
    const float* W2     = (const float*)d_in[6];
    const float* b2     = (const float*)d_in[7];
    const float* gamma2 = (const float*)d_in[8];
    const float* beta2  = (const float*)d_in[9];
    const float* Wfc    = (const float*)d_in[10];
    const float* bfc    = (const float*)d_in[11];
    float* out = (float*)d_out;

    int E = in_sizes[1] / 2;
    if (E > EMAX) E = EMAX;

    uint4*  pH;
    float4 *pB, *pC;
    float *ps1, *ps2;
    cudaGetSymbolAddress((void**)&pH, g_h16);
    cudaGetSymbolAddress((void**)&pB, g_bufB);
    cudaGetSymbolAddress((void**)&pC, g_bufC);
    cudaGetSymbolAddress((void**)&ps1, g_stats1);
    cudaGetSymbolAddress((void**)&ps2, g_stats2);

    const int smem64 = (128 * 65 + 64 * 64 + 64) * (int)sizeof(float);
    const int smem32 = (128 * 65 + 64 * 32 + 32) * (int)sizeof(float);
    cudaFuncSetAttribute((const void*)k_gemm<64, true, true>,
                         cudaFuncAttributeMaxDynamicSharedMemorySize, smem64);
    cudaFuncSetAttribute((const void*)k_gemm<32, false, false>,
                         cudaFuncAttributeMaxDynamicSharedMemorySize, smem32);

    const int GB = (NN + 127) / 128;
    const int EB = (E + 255) / 256;
    const int ZB = (NN * 16 + 255) / 256;            // 6250
    long scat_items = (long)E * 8;
    int SB = (int)((scat_items + 255) / 256);

    k_pre<<<ZB, 256>>>((const unsigned int*)ei);                       // #1
    k_cvtdeg<<<EB, 256>>>(ei, E);                                      // #2

    // layer 1: hs1(fp16) = (x@W1)*dinv -> scat -> epi(relu+stats, zero acc)
    k_gemm<64, true, true><<<GB, 128, smem64>>>(
        x, W1, nullptr, nullptr, nullptr, nullptr, pH);                // #3
    k_scat<<<SB, 256>>>(pH, pB, E);                                    // #4 PROFILED
    k_epi<true><<<ZB, 256>>>((const uint2*)pH, pB, b1, pC, ps1);       // #5

    // layer 2: hs2(fp16) = ((a1*h1+c1)@W2)*dinv -> scat -> epi
    k_gemm<64, true, true><<<GB, 128, smem64>>>(
        (const float*)pC, W2, ps1, gamma1, beta1, nullptr, pH);        // #6
    k_scat<<<SB, 256>>>(pH, pB, E);                                    // #7
    k_epi<false><<<ZB, 256>>>((const uint2*)pH, pB, b2, pC, ps2);      // #8

    // final: out = (a2*h2+c2)@Wfc + (bfc + c2@Wfc)
    k_gemm<32, false, false><<<GB, 128, smem32>>>(
        (const float*)pC, Wfc, ps2, gamma2, beta2, bfc, out);          // #9
}

// round 11
// speedup vs baseline: 1.3633x; 1.3633x over previous
#include <cuda_runtime.h>

#define NN 100000
#define HH 64
#define EMAX 1600000
#define SLOTS 8
#define BN_EPS 1e-5f
#define NB_SCAN 391   // ceil(NN/256)

// ---- scratch ----
__device__ float4 g_bufA[NN * HH / 4];            // hs (dinv-scaled features)
__device__ float4 g_bufB[NN * HH / 4];            // fp32 accumulator
__device__ float4 g_bufC[NN * HH / 4];            // layer outputs
__device__ __align__(16) int g_srcc[EMAX];        // CSR-ordered src
__device__ __align__(16) int g_dstc[EMAX];        // CSR-ordered dst
__device__ int   g_degi[NN];
__device__ int   g_cur[NN];
__device__ int   g_bsum[NB_SCAN];
__device__ int   g_is64;
__device__ float g_stats1[128 * 32];              // padded: ch at [ch*32]
__device__ float g_stats2[128 * 32];

// ---- 1: zero acc/deg/stats; block 0 detects int64 vs int32 ----
__global__ void k_pre(const unsigned int* __restrict__ ei) {
    int i = blockIdx.x * 256 + threadIdx.x;
    if (i < NN * HH / 4) g_bufB[i] = make_float4(0.f, 0.f, 0.f, 0.f);
    if (i < NN) g_degi[i] = 0;
    if (i < 128 * 32) { g_stats1[i] = 0.0f; g_stats2[i] = 0.0f; }
    if (blockIdx.x == 0) {
        __shared__ unsigned int s;
        if (threadIdx.x == 0) s = 0u;
        __syncthreads();
        atomicOr(&s, ei[threadIdx.x * 2 + 1]);   // high words if int64
        __syncthreads();
        if (threadIdx.x == 0) g_is64 = (s == 0u) ? 1 : 0;
    }
}

// ---- 2: in-degree ----
__global__ void k_deg(const void* __restrict__ ei, int E) {
    int e = blockIdx.x * 256 + threadIdx.x;
    if (e >= E) return;
    int d = g_is64 ? (int)((const long long*)ei)[E + e] : ((const int*)ei)[E + e];
    atomicAdd(&g_degi[d], 1);
}

// ---- 3: per-block degree sums ----
__global__ void __launch_bounds__(256) k_scanA() {
    __shared__ int sp[256];
    int i = blockIdx.x * 256 + threadIdx.x;
    int c = (i < NN) ? g_degi[i] : 0;
    sp[threadIdx.x] = c;
    __syncthreads();
    for (int o = 128; o > 0; o >>= 1) {
        if (threadIdx.x < o) sp[threadIdx.x] += sp[threadIdx.x + o];
        __syncthreads();
    }
    if (threadIdx.x == 0) g_bsum[blockIdx.x] = sp[0];
}

// ---- 4: scan block sums (1 block) ----
__global__ void __launch_bounds__(512) k_scanB() {
    __shared__ int sp[512];
    int t = threadIdx.x;
    sp[t] = (t < NB_SCAN) ? g_bsum[t] : 0;
    __syncthreads();
    for (int o = 1; o < 512; o <<= 1) {
        int v = (t >= o) ? sp[t - o] : 0;
        __syncthreads();
        sp[t] += v;
        __syncthreads();
    }
    if (t < NB_SCAN) g_bsum[t] = sp[t] - ((t < NB_SCAN) ? g_bsum[t] : 0) + 0; // placeholder
    // rewrite exclusively: recompute properly below
    __syncthreads();
    // sp now holds inclusive sums; exclusive = inclusive - original. Store exclusive:
    // (original already overwritten above is wrong; do it in one pass instead)
}

// NOTE: scanB above is subtle; replaced by a correct simple version:
__global__ void __launch_bounds__(512) k_scanB2() {
    __shared__ int orig[512], incl[512];
    int t = threadIdx.x;
    int v = (t < NB_SCAN) ? g_bsum[t] : 0;
    orig[t] = v; incl[t] = v;
    __syncthreads();
    for (int o = 1; o < 512; o <<= 1) {
        int u = (t >= o) ? incl[t - o] : 0;
        __syncthreads();
        incl[t] += u;
        __syncthreads();
    }
    if (t < NB_SCAN) g_bsum[t] = incl[t] - orig[t];   // exclusive prefix
}

// ---- 5: per-node offsets (cursor) ----
__global__ void __launch_bounds__(256) k_scanC() {
    __shared__ int sp[256];
    int i = blockIdx.x * 256 + threadIdx.x;
    int c = (i < NN) ? g_degi[i] : 0;
    sp[threadIdx.x] = c;
    __syncthreads();
    for (int o = 1; o < 256; o <<= 1) {
        int v = (threadIdx.x >= o) ? sp[threadIdx.x - o] : 0;
        __syncthreads();
        sp[threadIdx.x] += v;
        __syncthreads();
    }
    if (i < NN) g_cur[i] = g_bsum[blockIdx.x] + sp[threadIdx.x] - c;  // exclusive
}

// ---- 6: CSR placement ----
__global__ void k_place(const void* __restrict__ ei, int E) {
    int e = blockIdx.x * 256 + threadIdx.x;
    if (e >= E) return;
    int s, d;
    if (g_is64) {
        const long long* p = (const long long*)ei;
        s = (int)p[e]; d = (int)p[E + e];
    } else {
        const int* p = (const int*)ei;
        s = p[e]; d = p[E + e];
    }
    int pos = atomicAdd(&g_cur[d], 1);
    g_srcc[pos] = s;
    g_dstc[pos] = d;
}

// ---- GEMM: out[r] = ((a*X[r]+c)@W) * dinv[r] + (bias + c@W); BN from stats ----
template <int NOUT, bool SCALE>
__global__ void __launch_bounds__(128) k_gemm(
    const float* __restrict__ X, const float* __restrict__ Wg,
    const float* __restrict__ stats, const float* __restrict__ gamma,
    const float* __restrict__ beta,
    const float* __restrict__ bias, float* __restrict__ out)
{
    extern __shared__ float sm[];
    float* Xs   = sm;                 // 128*65
    float* Ws   = sm + 128 * 65;      // 64*NOUT
    float* Init = Ws + 64 * NOUT;
    __shared__ float sa[64], sc[64];

    const int t = threadIdx.x;
    const long row0 = (long)blockIdx.x * 128;

    if (t < 64) {
        float a = 1.0f, c = 0.0f;
        if (stats) {
            float mu  = stats[t * 32] * (1.0f / NN);
            float var = stats[(64 + t) * 32] * (1.0f / NN) - mu * mu;
            a = gamma[t] * rsqrtf(var + BN_EPS);
            c = beta[t] - mu * a;
        }
        sa[t] = a; sc[t] = c;
    }
    __syncthreads();

    #pragma unroll
    for (int i = 0; i < 16; i++) {
        int lin = t + i * 128;
        int r = lin >> 4, q = lin & 15;
        long gr = row0 + r;
        float4 v = (gr < NN) ? reinterpret_cast<const float4*>(X)[gr * 16 + q]
                             : make_float4(0.f, 0.f, 0.f, 0.f);
        float* p = &Xs[r * 65 + q * 4];
        p[0] = v.x; p[1] = v.y; p[2] = v.z; p[3] = v.w;
    }
    #pragma unroll
    for (int i = t; i < 16 * NOUT; i += 128) {
        int k = (i * 4) / NOUT;
        float a = sa[k];
        float4 w = reinterpret_cast<const float4*>(Wg)[i];
        reinterpret_cast<float4*>(Ws)[i] = make_float4(w.x * a, w.y * a, w.z * a, w.w * a);
    }
    if (t < NOUT) {
        float s = bias ? bias[t] : 0.0f;
        #pragma unroll 8
        for (int k = 0; k < 64; k++) s += sc[k] * Wg[k * NOUT + t];
        Init[t] = s;
    }
    __syncthreads();

    unsigned long long acc[NOUT / 2];
    #pragma unroll
    for (int j = 0; j < NOUT / 2; j++) {
        float2 iv = reinterpret_cast<const float2*>(Init)[j];
        asm("mov.b64 %0, {%1, %2};" : "=l"(acc[j]) : "f"(iv.x), "f"(iv.y));
    }
    const float* xr = &Xs[t * 65];
    #pragma unroll 4
    for (int k = 0; k < 64; k++) {
        float xv = xr[k];
        unsigned long long xx;
        asm("mov.b64 %0, {%1, %1};" : "=l"(xx) : "f"(xv));
        const unsigned long long* wr =
            reinterpret_cast<const unsigned long long*>(&Ws[k * NOUT]);
        #pragma unroll
        for (int j = 0; j < NOUT / 2; j++)
            asm("fma.rn.f32x2 %0, %1, %2, %0;" : "+l"(acc[j]) : "l"(xx), "l"(wr[j]));
    }

    long r = row0 + t;
    float rs = 1.0f;
    if (SCALE && r < NN) rs = rsqrtf((float)g_degi[r] + 1.0f);

    __syncthreads();
    #pragma unroll
    for (int j = 0; j < NOUT / 2; j++) {
        float lo, hi;
        asm("mov.b64 {%0, %1}, %2;" : "=f"(lo), "=f"(hi) : "l"(acc[j]));
        Xs[t * 65 + 2 * j]     = lo * rs;
        Xs[t * 65 + 2 * j + 1] = hi * rs;
    }
    __syncthreads();
    constexpr int Q = NOUT / 4;
    #pragma unroll
    for (int i = 0; i < Q; i++) {
        int lin = t + i * 128;
        int r2 = lin / Q, q = lin % Q;
        long gr = row0 + r2;
        if (gr < NN) {
            float* p = &Xs[r2 * 65 + q * 4];
            reinterpret_cast<float4*>(out)[gr * Q + q] = make_float4(p[0], p[1], p[2], p[3]);
        }
    }
}

__device__ __forceinline__ void red4(float4* p, float4 v) {
    asm volatile("red.global.add.v4.f32 [%0], {%1,%2,%3,%4};"
                 :: "l"(p), "f"(v.x), "f"(v.y), "f"(v.z), "f"(v.w) : "memory");
}
// predicated RED: single @p instruction, no BSSY divergence block
__device__ __forceinline__ void red4p(int pred, float4* p, float4 v) {
    asm volatile("{ .reg .pred pp; setp.ne.s32 pp, %0, 0;"
                 " @pp red.global.add.v4.f32 [%1], {%2,%3,%4,%5}; }"
                 :: "r"(pred), "l"(p), "f"(v.x), "f"(v.y), "f"(v.z), "f"(v.w)
                 : "memory");
}

// ---- segmented scatter over CSR order: thread = (8 slots, float4 q) ----
__global__ void __launch_bounds__(256) k_seg(
    const float4* __restrict__ hs, float4* __restrict__ acc, int E)
{
    long idx = (long)blockIdx.x * 256 + threadIdx.x;
    int sg = (int)(idx >> 4);
    int q = (int)(idx & 15);
    long s0 = (long)sg * SLOTS;
    if (s0 >= E) return;
    const bool full = (s0 + SLOTS <= E);

    int src[SLOTS], dst[SLOTS];
    if (full) {
        int4 sa = *reinterpret_cast<const int4*>(&g_srcc[s0]);
        int4 sb = *reinterpret_cast<const int4*>(&g_srcc[s0 + 4]);
        int4 da = *reinterpret_cast<const int4*>(&g_dstc[s0]);
        int4 db = *reinterpret_cast<const int4*>(&g_dstc[s0 + 4]);
        src[0]=sa.x; src[1]=sa.y; src[2]=sa.z; src[3]=sa.w;
        src[4]=sb.x; src[5]=sb.y; src[6]=sb.z; src[7]=sb.w;
        dst[0]=da.x; dst[1]=da.y; dst[2]=da.z; dst[3]=da.w;
        dst[4]=db.x; dst[5]=db.y; dst[6]=db.z; dst[7]=db.w;
    } else {
        #pragma unroll
        for (int i = 0; i < SLOTS; i++) {
            long s = s0 + i; if (s > E - 1) s = E - 1;
            src[i] = g_srcc[s];
            dst[i] = g_dstc[s];
        }
    }

    float4 v[SLOTS];
    #pragma unroll
    for (int i = 0; i < SLOTS; i++)
        v[i] = hs[(long)src[i] * 16 + q];
    if (!full) {
        #pragma unroll
        for (int i = 0; i < SLOTS; i++)
            if (s0 + i >= E) v[i] = make_float4(0.f, 0.f, 0.f, 0.f);
    }

    float4 a = v[0];
    int cur = dst[0];
    #pragma unroll
    for (int i = 1; i < SLOTS; i++) {
        int brk = (dst[i] != cur) ? 1 : 0;
        red4p(brk, &acc[(long)cur * 16 + q], a);
        a.x = brk ? v[i].x : a.x + v[i].x;
        a.y = brk ? v[i].y : a.y + v[i].y;
        a.z = brk ? v[i].z : a.z + v[i].z;
        a.w = brk ? v[i].w : a.w + v[i].w;
        cur = dst[i];
    }
    red4(&acc[(long)cur * 16 + q], a);
}

// ---- epilogue: h = relu(dinv*(acc+hs)+b); BN stats; optionally re-zero acc ----
template <bool ZERO_ACC>
__global__ void k_epi(const float4* hs, float4* acc, const float* __restrict__ bias,
                      float4* out, float* __restrict__ stats)
{
    __shared__ float ssum[64], ssq[64];
    int t = threadIdx.x;
    if (t < 64) { ssum[t] = 0.0f; ssq[t] = 0.0f; }
    __syncthreads();
    long idx = (long)blockIdx.x * 256 + t;
    if (idx < (long)NN * 16) {
        int v = (int)(idx >> 4);
        int q = (int)(idx & 15);
        float4 a = acc[idx];
        float4 h = hs[idx];
        float di = rsqrtf((float)g_degi[v] + 1.0f);
        float4 b = reinterpret_cast<const float4*>(bias)[q];
        float4 o;
        o.x = fmaxf(fmaf(di, a.x + h.x, b.x), 0.0f);
        o.y = fmaxf(fmaf(di, a.y + h.y, b.y), 0.0f);
        o.z = fmaxf(fmaf(di, a.z + h.z, b.z), 0.0f);
        o.w = fmaxf(fmaf(di, a.w + h.w, b.w), 0.0f);
        out[idx] = o;
        if (ZERO_ACC) acc[idx] = make_float4(0.f, 0.f, 0.f, 0.f);
        int j = q * 4;
        atomicAdd(&ssum[j + 0], o.x); atomicAdd(&ssq[j + 0], o.x * o.x);
        atomicAdd(&ssum[j + 1], o.y); atomicAdd(&ssq[j + 1], o.y * o.y);
        atomicAdd(&ssum[j + 2], o.z); atomicAdd(&ssq[j + 2], o.z * o.z);
        atomicAdd(&ssum[j + 3], o.w); atomicAdd(&ssq[j + 3], o.w * o.w);
    }
    __syncthreads();
    if (t < 64) {
        atomicAdd(&stats[t * 32], ssum[t]);
        atomicAdd(&stats[(64 + t) * 32], ssq[t]);
    }
}

extern "C" void kernel_launch(void* const* d_in, const int* in_sizes, int n_in,
                              void* d_out, int out_size)
{
    const float* x      = (const float*)d_in[0];
    const void*  ei     = d_in[1];
    const float* W1     = (const float*)d_in[2];
    const float* b1     = (const float*)d_in[3];
    const float* gamma1 = (const float*)d_in[4];
    const float* beta1  = (const float*)d_in[5];
    const float* W2     = (const float*)d_in[6];
    const float* b2     = (const float*)d_in[7];
    const float* gamma2 = (const float*)d_in[8];
    const float* beta2  = (const float*)d_in[9];
    const float* Wfc    = (const float*)d_in[10];
    const float* bfc    = (const float*)d_in[11];
    float* out = (float*)d_out;

    int E = in_sizes[1] / 2;
    if (E > EMAX) E = EMAX;

    float4 *pA, *pB, *pC;
    float *ps1, *ps2;
    cudaGetSymbolAddress((void**)&pA, g_bufA);
    cudaGetSymbolAddress((void**)&pB, g_bufB);
    cudaGetSymbolAddress((void**)&pC, g_bufC);
    cudaGetSymbolAddress((void**)&ps1, g_stats1);
    cudaGetSymbolAddress((void**)&ps2, g_stats2);

    const int smem64 = (128 * 65 + 64 * 64 + 64) * (int)sizeof(float);
    const int smem32 = (128 * 65 + 64 * 32 + 32) * (int)sizeof(float);
    cudaFuncSetAttribute((const void*)k_gemm<64, true>,
                         cudaFuncAttributeMaxDynamicSharedMemorySize, smem64);
    cudaFuncSetAttribute((const void*)k_gemm<32, false>,
                         cudaFuncAttributeMaxDynamicSharedMemorySize, smem32);

    const int GB = (NN + 127) / 128;
    const int EB = (E + 255) / 256;
    const int ZB = (NN * 16 + 255) / 256;            // 6250
    long segt = ((long)(E + SLOTS - 1) / SLOTS) * 16;
    int SB = (int)((segt + 255) / 256);

    k_pre<<<ZB, 256>>>((const unsigned int*)ei);     // 1
    k_deg<<<EB, 256>>>(ei, E);                       // 2
    k_scanA<<<NB_SCAN, 256>>>();                     // 3
    k_scanB2<<<1, 512>>>();                          // 4
    k_scanC<<<NB_SCAN, 256>>>();                     // 5
    k_place<<<EB, 256>>>(ei, E);                     // 6

    // layer 1
    k_gemm<64, true><<<GB, 128, smem64>>>(
        x, W1, nullptr, nullptr, nullptr, nullptr, (float*)pA);        // 7
    k_seg<<<SB, 256>>>(pA, pB, E);                                     // 8
    k_epi<true><<<ZB, 256>>>(pA, pB, b1, pC, ps1);                     // 9

    // layer 2
    k_gemm<64, true><<<GB, 128, smem64>>>(
        (const float*)pC, W2, ps1, gamma1, beta1, nullptr, (float*)pA);// 10
    k_seg<<<SB, 256>>>(pA, pB, E);                                     // 11
    k_epi<false><<<ZB, 256>>>(pA, pB, b2, pC, ps2);                    // 12

    // final
    k_gemm<32, false><<<GB, 128, smem32>>>(
        (const float*)pC, Wfc, ps2, gamma2, beta2, bfc, out);          // 13
}